// round 1
// baseline (speedup 1.0000x reference)
#include <cuda_runtime.h>
#include <cstdint>

#define B_SZ 8
#define SEQ 4096
#define DM 1024
#define DS 64
#define LTAPS 64

#define TBLK 128   // time steps per block
#define CBLK 64    // channels per block (32 float2 pairs)
#define TT 16      // outputs per thread
#define G 8        // tap group size

__device__ float g_Csum[DS];
__device__ float g_K[LTAPS * DM];   // K[l][c], channel-contiguous

// ---------------- prep kernels ----------------

__global__ void csum_kernel(const float* __restrict__ C) {
    int d = threadIdx.x;  // 64 threads
    float s = 0.f;
    #pragma unroll 8
    for (int m = 0; m < DM; ++m) s += C[m * DS + d];
    g_Csum[d] = s;
}

__global__ void kbuild_kernel(const float* __restrict__ A,
                              const float* __restrict__ Bp,
                              const float* __restrict__ log_dt) {
    int c = blockIdx.x * blockDim.x + threadIdx.x;  // 1024 threads total
    if (c >= DM) return;
    float dt = expf(log_dt[c]);
    float k[LTAPS];
    #pragma unroll
    for (int l = 0; l < LTAPS; ++l) k[l] = 0.f;
    for (int d = 0; d < DS; ++d) {
        float w = g_Csum[d] * Bp[d * DM + c];
        float r = expf(A[d] * dt);
        float p = w;
        #pragma unroll
        for (int l = 0; l < LTAPS; ++l) { k[l] += p; p *= r; }
    }
    #pragma unroll
    for (int l = 0; l < LTAPS; ++l) g_K[l * DM + c] = k[l];
}

// ---------------- packed f32x2 FMA (Blackwell FFMA2, PTX-only) ----------------

__device__ __forceinline__ float2 ffma2(float2 a, float2 b, float2 c) {
    float2 d;
    asm("fma.rn.f32x2 %0, %1, %2, %3;"
        : "=l"(*reinterpret_cast<unsigned long long*>(&d))
        : "l"(*reinterpret_cast<const unsigned long long*>(&a)),
          "l"(*reinterpret_cast<const unsigned long long*>(&b)),
          "l"(*reinterpret_cast<const unsigned long long*>(&c)));
    return d;
}

__device__ __forceinline__ float2 fmul2(float2 a, float2 b) {
    float2 d;
    asm("mul.rn.f32x2 %0, %1, %2;"
        : "=l"(*reinterpret_cast<unsigned long long*>(&d))
        : "l"(*reinterpret_cast<const unsigned long long*>(&a)),
          "l"(*reinterpret_cast<const unsigned long long*>(&b)));
    return d;
}

// ---------------- conv kernel ----------------
// y[b,t,c] = D[c]*u[b,t,c] + sum_{l=0}^{63} K[l,c] * u[b, t+31-l, c]

__global__ __launch_bounds__(256, 2)
void conv_kernel(const float* __restrict__ u,
                 const float* __restrict__ Dp,
                 float* __restrict__ y) {
    // shared u tile: time extent TBLK+64 (left halo 32, right halo 32),
    // 32 float2 channel-pairs. 192*32*8 = 49152 B (exactly 48KB).
    __shared__ float2 sh[TBLK + 64][CBLK / 2];

    const int b  = blockIdx.z;
    const int t0 = blockIdx.x * TBLK;
    const int c0 = blockIdx.y * CBLK;
    const int tid = threadIdx.x;

    const float2* __restrict__ u2 =
        reinterpret_cast<const float2*>(u + (size_t)b * SEQ * DM + c0);

    // cooperative coalesced load of the tile (with halo, zero-padded)
    for (int i = tid; i < (TBLK + 64) * 32; i += 256) {
        int tt = i >> 5;
        int p  = i & 31;
        int t  = t0 - 32 + tt;
        float2 v = make_float2(0.f, 0.f);
        if (t >= 0 && t < SEQ) v = u2[(size_t)t * (DM / 2) + p];
        sh[tt][p] = v;
    }
    __syncthreads();

    const int p   = tid & 31;          // channel pair within tile
    const int tg  = tid >> 5;          // time group (0..7)
    const int lt0 = 32 + tg * TT;      // shared time index of output j=0

    const float2 d2 = reinterpret_cast<const float2*>(Dp + c0)[p];

    // acc init = D * u_center
    float2 acc[TT];
    #pragma unroll
    for (int j = 0; j < TT; ++j)
        acc[j] = fmul2(d2, sh[lt0 + j][p]);

    // K pointer for this channel pair: K[l][c0+2p] as float2
    const float2* __restrict__ Kp =
        reinterpret_cast<const float2*>(g_K) + (c0 >> 1) + p;

    // register sliding window over tap groups.
    // group g covers taps l in [8g, 8g+8); u idx = lt + j + 31 - l.
    // window base for group g: wb_g = lt0 + 32 - 8g - G
    float2 w[TT + G - 1];
    const int wb0 = lt0 + 32 - G;   // = lt0 + 24
    #pragma unroll
    for (int i = 0; i < TT + G - 1; ++i) w[i] = sh[wb0 + i][p];

    #pragma unroll
    for (int g = 0; g < LTAPS / G; ++g) {
        if (g > 0) {
            // shift window up by G (wbase decreased by G)
            #pragma unroll
            for (int i = TT + G - 2; i >= G; --i) w[i] = w[i - G];
            const int wb = wb0 - g * G;
            #pragma unroll
            for (int i = 0; i < G; ++i) w[i] = sh[wb + i][p];
        }
        #pragma unroll
        for (int e = 0; e < G; ++e) {
            const int l = g * G + e;
            float2 k2 = Kp[l * (DM / 2)];
            #pragma unroll
            for (int j = 0; j < TT; ++j)
                acc[j] = ffma2(k2, w[j + (G - 1 - e)], acc[j]);
        }
    }

    // store
    float2* __restrict__ y2 =
        reinterpret_cast<float2*>(y + (size_t)b * SEQ * DM + c0);
    #pragma unroll
    for (int j = 0; j < TT; ++j) {
        int t = t0 + tg * TT + j;
        y2[(size_t)t * (DM / 2) + p] = acc[j];
    }
}

// ---------------- launch ----------------

extern "C" void kernel_launch(void* const* d_in, const int* in_sizes, int n_in,
                              void* d_out, int out_size) {
    const float* u      = (const float*)d_in[0];
    const float* A      = (const float*)d_in[1];
    const float* Bp     = (const float*)d_in[2];
    const float* C      = (const float*)d_in[3];
    const float* Dp     = (const float*)d_in[4];
    const float* log_dt = (const float*)d_in[5];
    float* y = (float*)d_out;

    csum_kernel<<<1, 64>>>(C);
    kbuild_kernel<<<4, 256>>>(A, Bp, log_dt);

    dim3 grid(SEQ / TBLK, DM / CBLK, B_SZ);  // (32, 16, 8)
    conv_kernel<<<grid, 256>>>(u, Dp, y);
}

// round 2
// speedup vs baseline: 1.2416x; 1.2416x over previous
#include <cuda_runtime.h>
#include <cstdint>

#define B_SZ 8
#define SEQ 4096
#define DM 1024
#define DS 64
#define LTAPS 64

#define TBLK 128   // time steps per block
#define CBLK 64    // channels per block (32 float2 pairs)
#define TT 16      // outputs per thread
#define G 8        // tap group size

__device__ float g_K[LTAPS * DM];   // K[l][c], channel-contiguous

// ---------------- fused prep kernel: Csum + K build ----------------
// 4 blocks x 256 threads; each block covers 256 channels.
// Step 1 (per block, redundant): Csum[d] = sum_m C[m][d], cooperative+coalesced.
// Step 2: per-channel K[l][c] = sum_d Csum[d]*B[d][c]*exp(A[d]*dt_c)^l.

__global__ __launch_bounds__(256)
void kbuild_kernel(const float* __restrict__ A,
                   const float* __restrict__ Bp,
                   const float* __restrict__ C,
                   const float* __restrict__ log_dt) {
    __shared__ float sh_part[4][DS];
    __shared__ float sh_csum[DS];

    const int tid = threadIdx.x;

    // --- cooperative column sum of C (coalesced: consecutive tid -> consecutive addr)
    {
        const int d     = tid & 63;
        const int slice = tid >> 6;          // 0..3, each slice covers 256 m-rows
        const float* __restrict__ Cp = C + (size_t)(slice * 256) * DS + d;
        float s = 0.f;
        #pragma unroll 8
        for (int i = 0; i < 256; ++i) s += Cp[(size_t)i * DS];
        sh_part[slice][d] = s;
    }
    __syncthreads();
    if (tid < DS)
        sh_csum[tid] = sh_part[0][tid] + sh_part[1][tid] +
                       sh_part[2][tid] + sh_part[3][tid];
    __syncthreads();

    // --- per-channel kernel taps
    const int c = blockIdx.x * 256 + tid;    // 0..1023
    const float dt = expf(log_dt[c]);

    float k[LTAPS];
    #pragma unroll
    for (int l = 0; l < LTAPS; ++l) k[l] = 0.f;

    #pragma unroll 2
    for (int d = 0; d < DS; ++d) {
        const float w = sh_csum[d] * Bp[(size_t)d * DM + c];
        const float r = expf(A[d] * dt);
        float p = w;
        #pragma unroll
        for (int l = 0; l < LTAPS; ++l) { k[l] += p; p *= r; }
    }

    #pragma unroll
    for (int l = 0; l < LTAPS; ++l) g_K[(size_t)l * DM + c] = k[l];
}

// ---------------- packed f32x2 FMA (Blackwell FFMA2, PTX-only) ----------------

__device__ __forceinline__ float2 ffma2(float2 a, float2 b, float2 c) {
    float2 d;
    asm("fma.rn.f32x2 %0, %1, %2, %3;"
        : "=l"(*reinterpret_cast<unsigned long long*>(&d))
        : "l"(*reinterpret_cast<const unsigned long long*>(&a)),
          "l"(*reinterpret_cast<const unsigned long long*>(&b)),
          "l"(*reinterpret_cast<const unsigned long long*>(&c)));
    return d;
}

__device__ __forceinline__ float2 fmul2(float2 a, float2 b) {
    float2 d;
    asm("mul.rn.f32x2 %0, %1, %2;"
        : "=l"(*reinterpret_cast<unsigned long long*>(&d))
        : "l"(*reinterpret_cast<const unsigned long long*>(&a)),
          "l"(*reinterpret_cast<const unsigned long long*>(&b)));
    return d;
}

// ---------------- conv kernel ----------------
// y[b,t,c] = D[c]*u[b,t,c] + sum_{l=0}^{63} K[l,c] * u[b, t+31-l, c]

__global__ __launch_bounds__(256, 2)
void conv_kernel(const float* __restrict__ u,
                 const float* __restrict__ Dp,
                 float* __restrict__ y) {
    // shared u tile: time extent TBLK+64 (left halo 32, right halo 32),
    // 32 float2 channel-pairs. 192*32*8 = 49152 B (exactly 48KB).
    __shared__ float2 sh[TBLK + 64][CBLK / 2];

    const int b  = blockIdx.z;
    const int t0 = blockIdx.x * TBLK;
    const int c0 = blockIdx.y * CBLK;
    const int tid = threadIdx.x;

    const float2* __restrict__ u2 =
        reinterpret_cast<const float2*>(u + (size_t)b * SEQ * DM + c0);

    // cooperative coalesced load of the tile (with halo, zero-padded)
    for (int i = tid; i < (TBLK + 64) * 32; i += 256) {
        int tt = i >> 5;
        int p  = i & 31;
        int t  = t0 - 32 + tt;
        float2 v = make_float2(0.f, 0.f);
        if (t >= 0 && t < SEQ) v = u2[(size_t)t * (DM / 2) + p];
        sh[tt][p] = v;
    }
    __syncthreads();

    const int p   = tid & 31;          // channel pair within tile
    const int tg  = tid >> 5;          // time group (0..7)
    const int lt0 = 32 + tg * TT;      // shared time index of output j=0

    const float2 d2 = reinterpret_cast<const float2*>(Dp + c0)[p];

    // acc init = D * u_center
    float2 acc[TT];
    #pragma unroll
    for (int j = 0; j < TT; ++j)
        acc[j] = fmul2(d2, sh[lt0 + j][p]);

    // K pointer for this channel pair: K[l][c0+2p] as float2
    const float2* __restrict__ Kp =
        reinterpret_cast<const float2*>(g_K) + (c0 >> 1) + p;

    // register sliding window over tap groups.
    // group g covers taps l in [8g, 8g+8); u idx = lt + j + 31 - l.
    float2 w[TT + G - 1];
    const int wb0 = lt0 + 32 - G;   // = lt0 + 24
    #pragma unroll
    for (int i = 0; i < TT + G - 1; ++i) w[i] = sh[wb0 + i][p];

    #pragma unroll
    for (int g = 0; g < LTAPS / G; ++g) {
        if (g > 0) {
            // shift window up by G (wbase decreased by G)
            #pragma unroll
            for (int i = TT + G - 2; i >= G; --i) w[i] = w[i - G];
            const int wb = wb0 - g * G;
            #pragma unroll
            for (int i = 0; i < G; ++i) w[i] = sh[wb + i][p];
        }
        #pragma unroll
        for (int e = 0; e < G; ++e) {
            const int l = g * G + e;
            float2 k2 = Kp[l * (DM / 2)];
            #pragma unroll
            for (int j = 0; j < TT; ++j)
                acc[j] = ffma2(k2, w[j + (G - 1 - e)], acc[j]);
        }
    }

    // store
    float2* __restrict__ y2 =
        reinterpret_cast<float2*>(y + (size_t)b * SEQ * DM + c0);
    #pragma unroll
    for (int j = 0; j < TT; ++j) {
        int t = t0 + tg * TT + j;
        y2[(size_t)t * (DM / 2) + p] = acc[j];
    }
}

// ---------------- launch ----------------

extern "C" void kernel_launch(void* const* d_in, const int* in_sizes, int n_in,
                              void* d_out, int out_size) {
    const float* u      = (const float*)d_in[0];
    const float* A      = (const float*)d_in[1];
    const float* Bp     = (const float*)d_in[2];
    const float* C      = (const float*)d_in[3];
    const float* Dp     = (const float*)d_in[4];
    const float* log_dt = (const float*)d_in[5];
    float* y = (float*)d_out;

    kbuild_kernel<<<4, 256>>>(A, Bp, C, log_dt);

    dim3 grid(SEQ / TBLK, DM / CBLK, B_SZ);  // (32, 16, 8)
    conv_kernel<<<grid, 256>>>(u, Dp, y);
}

// round 3
// speedup vs baseline: 1.7577x; 1.4157x over previous
#include <cuda_runtime.h>
#include <cstdint>

#define B_SZ 8
#define SEQ 4096
#define DM 1024
#define DS 64
#define LTAPS 64

#define TBLK 128   // time steps per block
#define CBLK 64    // channels per block (32 float2 pairs)
#define TT 8       // outputs per thread
#define NTG 16     // time groups per block
#define NTHR 512   // conv block size
#define G 8        // tap group size

__device__ float g_part[64 * DS];   // partial C column sums
__device__ float g_K[LTAPS * DM];   // K[l][c], channel-contiguous

// ---------------- prep: stage A — partial column sums of C ----------------
// grid 64 x block 64; block j reduces rows m in [16j, 16j+16).
__global__ __launch_bounds__(64)
void csum_part_kernel(const float* __restrict__ C) {
    const int d = threadIdx.x;
    const float* __restrict__ Cp = C + (size_t)blockIdx.x * 16 * DS + d;
    float s = 0.f;
    #pragma unroll
    for (int i = 0; i < 16; ++i) s += Cp[(size_t)i * DS];
    g_part[blockIdx.x * DS + d] = s;
}

// ---------------- prep: stage B + K build ----------------
// grid 16 x block 64; block covers 64 channels.
__global__ __launch_bounds__(64)
void kbuild_kernel(const float* __restrict__ A,
                   const float* __restrict__ Bp,
                   const float* __restrict__ log_dt) {
    __shared__ float sh_csum[DS];
    const int tid = threadIdx.x;

    // finish the C column sum (64 partials per d, MLP via unroll)
    {
        float s = 0.f;
        #pragma unroll 16
        for (int j = 0; j < 64; ++j) s += g_part[j * DS + tid];
        sh_csum[tid] = s;
    }
    __syncthreads();

    const int c = blockIdx.x * 64 + tid;
    const float dt = expf(log_dt[c]);

    float k[LTAPS];
    #pragma unroll
    for (int l = 0; l < LTAPS; ++l) k[l] = 0.f;

    // unroll 4 -> four independent geometric chains in flight
    #pragma unroll 4
    for (int d = 0; d < DS; ++d) {
        const float w = sh_csum[d] * Bp[(size_t)d * DM + c];
        const float r = expf(A[d] * dt);
        float p = w;
        #pragma unroll
        for (int l = 0; l < LTAPS; ++l) { k[l] += p; p *= r; }
    }

    #pragma unroll
    for (int l = 0; l < LTAPS; ++l) g_K[(size_t)l * DM + c] = k[l];
}

// ---------------- packed f32x2 FMA (Blackwell FFMA2, PTX-only) ----------------

__device__ __forceinline__ float2 ffma2(float2 a, float2 b, float2 c) {
    float2 d;
    asm("fma.rn.f32x2 %0, %1, %2, %3;"
        : "=l"(*reinterpret_cast<unsigned long long*>(&d))
        : "l"(*reinterpret_cast<const unsigned long long*>(&a)),
          "l"(*reinterpret_cast<const unsigned long long*>(&b)),
          "l"(*reinterpret_cast<const unsigned long long*>(&c)));
    return d;
}

__device__ __forceinline__ float2 fmul2(float2 a, float2 b) {
    float2 d;
    asm("mul.rn.f32x2 %0, %1, %2;"
        : "=l"(*reinterpret_cast<unsigned long long*>(&d))
        : "l"(*reinterpret_cast<const unsigned long long*>(&a)),
          "l"(*reinterpret_cast<const unsigned long long*>(&b)));
    return d;
}

// ---------------- conv kernel ----------------
// y[b,t,c] = D[c]*u[b,t,c] + sum_{l=0}^{63} K[l,c] * u[b, t+31-l, c]
// 512 threads: 32 channel-pairs x 16 time groups x TT=8 outputs.
// Forced 2 CTAs/SM (64-reg cap) -> 32 warps/SM for latency hiding.

__global__ __launch_bounds__(NTHR, 2)
void conv_kernel(const float* __restrict__ u,
                 const float* __restrict__ Dp,
                 float* __restrict__ y) {
    // u tile: 192 time rows (halo 32 each side) x 32 float2 pairs = 48KB
    __shared__ float2 sh[TBLK + 64][CBLK / 2];

    const int b  = blockIdx.z;
    const int t0 = blockIdx.x * TBLK;
    const int c0 = blockIdx.y * CBLK;
    const int tid = threadIdx.x;

    const float2* __restrict__ u2 =
        reinterpret_cast<const float2*>(u + (size_t)b * SEQ * DM + c0);

    // cooperative coalesced tile load (zero-padded halo)
    #pragma unroll
    for (int it = 0; it < (TBLK + 64) * 32 / NTHR; ++it) {
        int i  = it * NTHR + tid;
        int tt = i >> 5;
        int p  = i & 31;
        int t  = t0 - 32 + tt;
        float2 v = make_float2(0.f, 0.f);
        if (t >= 0 && t < SEQ) v = u2[(size_t)t * (DM / 2) + p];
        sh[tt][p] = v;
    }
    __syncthreads();

    const int p   = tid & 31;          // channel pair
    const int tg  = tid >> 5;          // time group (0..15)
    const int lt0 = 32 + tg * TT;      // shared time index of output j=0

    const float2 d2 = reinterpret_cast<const float2*>(Dp + c0)[p];

    float2 acc[TT];
    #pragma unroll
    for (int j = 0; j < TT; ++j)
        acc[j] = fmul2(d2, sh[lt0 + j][p]);

    const float2* __restrict__ Kp =
        reinterpret_cast<const float2*>(g_K) + (c0 >> 1) + p;

    // register sliding window: 15 float2 covering sh[wb .. wb+14]
    float2 w[TT + G - 1];
    const int wb0 = lt0 + 32 - G;   // = lt0 + 24
    #pragma unroll
    for (int i = 0; i < TT + G - 1; ++i) w[i] = sh[wb0 + i][p];

    #pragma unroll
    for (int g = 0; g < LTAPS / G; ++g) {
        if (g > 0) {
            #pragma unroll
            for (int i = TT + G - 2; i >= G; --i) w[i] = w[i - G];
            const int wb = wb0 - g * G;
            #pragma unroll
            for (int i = 0; i < G; ++i) w[i] = sh[wb + i][p];
        }
        #pragma unroll
        for (int e = 0; e < G; ++e) {
            const int l = g * G + e;
            float2 k2 = Kp[(size_t)l * (DM / 2)];
            #pragma unroll
            for (int j = 0; j < TT; ++j)
                acc[j] = ffma2(k2, w[j + (G - 1 - e)], acc[j]);
        }
    }

    float2* __restrict__ y2 =
        reinterpret_cast<float2*>(y + (size_t)b * SEQ * DM + c0);
    #pragma unroll
    for (int j = 0; j < TT; ++j) {
        int t = t0 + tg * TT + j;
        y2[(size_t)t * (DM / 2) + p] = acc[j];
    }
}

// ---------------- launch ----------------

extern "C" void kernel_launch(void* const* d_in, const int* in_sizes, int n_in,
                              void* d_out, int out_size) {
    const float* u      = (const float*)d_in[0];
    const float* A      = (const float*)d_in[1];
    const float* Bp     = (const float*)d_in[2];
    const float* C      = (const float*)d_in[3];
    const float* Dp     = (const float*)d_in[4];
    const float* log_dt = (const float*)d_in[5];
    float* y = (float*)d_out;

    csum_part_kernel<<<64, 64>>>(C);
    kbuild_kernel<<<16, 64>>>(A, Bp, log_dt);

    dim3 grid(SEQ / TBLK, DM / CBLK, B_SZ);  // (32, 16, 8)
    conv_kernel<<<grid, NTHR>>>(u, Dp, y);
}